// round 10
// baseline (speedup 1.0000x reference)
#include <cuda_runtime.h>

// NeighborlistForInference: brute-force N^2 upper-triangular pair list.
//
// Output layout (fp32, 6*P elements, P = n(n-1)/2):
//   [0   ,  P) : i index per pair (-1 if out of cutoff)
//   [P   , 2P) : j index per pair (-1)
//   [2P  , 3P) : d_ij (0)
//   [3P  , 6P) : r_ij row-major [P,3] (0)
//
// Round-7: combine R6's optimal loads with R4's optimal stores via smem.
//  * Staging: per row segment, FLAT contiguous copy pos[3*j0 ..] -> sj[3*q ..]
//    (lane-linear: every LDG.32 / STS.32 is a single L1 wavefront).
//  * Consumer thread t owns pairs p0=base+4t; reads its 12 floats with three
//    conflict-free 16B-aligned LDS.128; writes 6 x STG.128 (.cs).
//  * Math / PBC / mask bit-exact vs reference (rel_err 3e-8 expected).

#ifndef NL_CUTOFF
#define NL_CUTOFF 0.5f
#endif

#define BLOCK_THREADS   256
#define PAIRS_PER_BLOCK 1024

__device__ __forceinline__ int tri_start(int i, int n) {
    return (i * (2 * n - i - 1)) >> 1;     // row start, max ~36M fits int32
}

__device__ __forceinline__ int tri_row(int p, int n) {
    // row i with tri_start(i) <= p < tri_start(i+1); sqrt estimate + exact fixup
    const int a = 2 * n - 1;
    const int disc = a * a - 8 * p;
    int i = (int)(0.5f * ((float)a - sqrtf((float)disc)));
    if (i < 0) i = 0;
    if (i > n - 2) i = n - 2;
    while (p < tri_start(i, n)) --i;
    while (i < n - 2 && p >= tri_start(i + 1, n)) ++i;
    return i;
}

__global__ __launch_bounds__(BLOCK_THREADS)
void neighborlist_kernel(const float* __restrict__ pos,
                         const float* __restrict__ box,
                         const int*   __restrict__ is_periodic,
                         float* __restrict__ out_i,
                         float* __restrict__ out_j,
                         float* __restrict__ out_d,
                         float* __restrict__ out_r,
                         int n, int P)
{
    // pair-slot positions, interleaved xyz: sj[3q+c] = pos[3*j(base+q)+c]
    __shared__ __align__(16) float sj[3 * PAIRS_PER_BLOCK];   // 12 KB

    const int base    = blockIdx.x * PAIRS_PER_BLOCK;
    const int m_total = min(PAIRS_PER_BLOCK, P - base);

    // ---- staging: flat coalesced copy per row segment (j contiguous in row)
    {
        int q = 0;
        int i = tri_row(base, n);
        while (q < m_total) {
            const int rs  = tri_start(i, n);
            const int p   = base + q;
            const int j0  = i + 1 + (p - rs);
            const int seg = min(m_total - q, n - j0);      // pairs this segment
            const float* __restrict__ src = pos + 3 * j0;
            float* dst = sj + 3 * q;
            const int cnt = 3 * seg;
            for (int f = threadIdx.x; f < cnt; f += BLOCK_THREADS)
                dst[f] = src[f];                           // 1 wavefront / instr
            q += seg;
            ++i;
        }
    }
    __syncthreads();

    // ---- consumer: thread t owns pairs p0..p0+3 (blocked)
    const int p0 = base + 4 * threadIdx.x;
    if (p0 >= P) return;                     // P, base, m_total all %4 == 0

    int i = tri_row(p0, n);
    int j = i + 1 + (p0 - tri_start(i, n));

    const float Lx = box[0], Ly = box[4], Lz = box[8];
    const float hx = 0.5f * Lx, hy = 0.5f * Ly, hz = 0.5f * Lz;
    const int per = *is_periodic;

    float xi = pos[3 * i + 0], yi = pos[3 * i + 1], zi = pos[3 * i + 2];
    float fi_f = (float)i;
    float fj_f = (float)j;

    // 12 floats = this thread's 4 pairs (xyz interleaved), 3 x LDS.128,
    // 16B-aligned (48*t bytes), conflict-free within each quarter-warp phase.
    float v[12];
    {
        const float4* s4 = (const float4*)(sj + 12 * threadIdx.x);
        *(float4*)(v + 0) = s4[0];
        *(float4*)(v + 4) = s4[1];
        *(float4*)(v + 8) = s4[2];
    }

    float fi[4], fj[4], fd[4], rx[4], ry[4], rz[4];

    #pragma unroll
    for (int k = 0; k < 4; ++k) {
        if (j >= n) {                        // rare row crossing
            ++i; j = i + 1;
            xi = pos[3 * i + 0]; yi = pos[3 * i + 1]; zi = pos[3 * i + 2];
            fi_f = (float)i; fj_f = (float)j;
        }
        float dx = xi - v[3 * k + 0];
        float dy = yi - v[3 * k + 1];
        float dz = zi - v[3 * k + 2];
        if (per) {
            // exact minimum-image for r in (-L, L): t in (-L/2, 3L/2)
            float tx = dx + hx; tx = (tx >= Lx) ? tx - Lx : tx; tx = (tx < 0.0f) ? tx + Lx : tx; dx = tx - hx;
            float ty = dy + hy; ty = (ty >= Ly) ? ty - Ly : ty; ty = (ty < 0.0f) ? ty + Ly : ty; dy = ty - hy;
            float tz = dz + hz; tz = (tz >= Lz) ? tz - Lz : tz; tz = (tz < 0.0f) ? tz + Lz : tz; dz = tz - hz;
        }
        const float d  = sqrtf(dx * dx + dy * dy + dz * dz);   // IEEE
        const bool  in = (d <= NL_CUTOFF);
        fi[k] = in ? fi_f : -1.0f;
        fj[k] = in ? fj_f : -1.0f;
        fd[k] = in ? d    :  0.0f;
        rx[k] = in ? dx : 0.0f;
        ry[k] = in ? dy : 0.0f;
        rz[k] = in ? dz : 0.0f;
        ++j; fj_f += 1.0f;                   // exact: j < 2^24
    }

    // all six stream addresses 16B-aligned (p0 % 4 == 0)
    __stcs((float4*)(out_i + p0), make_float4(fi[0], fi[1], fi[2], fi[3]));
    __stcs((float4*)(out_j + p0), make_float4(fj[0], fj[1], fj[2], fj[3]));
    __stcs((float4*)(out_d + p0), make_float4(fd[0], fd[1], fd[2], fd[3]));
    float* rb = out_r + 3 * p0;              // 12 floats, 16B-aligned
    __stcs((float4*)(rb + 0), make_float4(rx[0], ry[0], rz[0], rx[1]));
    __stcs((float4*)(rb + 4), make_float4(ry[1], rz[1], rx[2], ry[2]));
    __stcs((float4*)(rb + 8), make_float4(rz[2], rx[3], ry[3], rz[3]));
}

extern "C" void kernel_launch(void* const* d_in, const int* in_sizes, int n_in,
                              void* d_out, int out_size)
{
    const float* pos   = (const float*)d_in[0];
    const float* box   = (const float*)d_in[1];
    const int*   isper = (const int*)d_in[2];
    float*       out   = (float*)d_out;

    const int n = in_sizes[0] / 3;
    const int P = (int)((long long)n * (n - 1) / 2);   // 17,997,000 for n=6000

    const int grid = (P + PAIRS_PER_BLOCK - 1) / PAIRS_PER_BLOCK;
    neighborlist_kernel<<<grid, BLOCK_THREADS>>>(pos, box, isper,
                                                 out,
                                                 out + P,
                                                 out + 2 * (size_t)P,
                                                 out + 3 * (size_t)P,
                                                 n, P);
}

// round 11
// speedup vs baseline: 1.5770x; 1.5770x over previous
#include <cuda_runtime.h>

// NeighborlistForInference: brute-force N^2 upper-triangular pair list.
//
// Output layout (fp32, 6*P elements, P = n(n-1)/2):
//   [0   ,  P) : i index per pair (-1 if out of cutoff)
//   [P   , 2P) : j index per pair (-1)
//   [2P  , 3P) : d_ij (0)
//   [3P  , 6P) : r_ij row-major [P,3] (0)
//
// Round-10 = R6 (strided warp mapping, 62.2us champion) + sparse fast path:
//  * mask via s <= 0x3E800001, exactly equivalent to (IEEE sqrtf(s) <= 0.5f)
//    (correctly-rounded sqrt is monotone; boundary float verified).
//  * if no lane in the warp is in-cutoff (~98.4% of iterations), outputs are
//    the constants (-1,-1,0,0,0,0): skip sqrt + selects and emit TWO
//    predicated STG.128s (lanes 0..23) covering the three 128B i/j/d blocks
//    and the 384B zero r block, instead of 6 scalar STGs per lane.
//  * slow path identical to R6 (bit-identical results, rel_err 3e-8).

#ifndef NL_CUTOFF
#define NL_CUTOFF 0.5f
#endif

#define BLOCK_THREADS 256   // 8 warps * 128 pairs = 1024 pairs per block

__device__ __forceinline__ int tri_start(int i, int n) {
    return (i * (2 * n - i - 1)) >> 1;     // row start, max ~36M fits int32
}

__device__ __forceinline__ int tri_row(int p, int n) {
    const int a = 2 * n - 1;
    const int disc = a * a - 8 * p;
    int i = (int)(0.5f * ((float)a - sqrtf((float)disc)));
    if (i < 0) i = 0;
    if (i > n - 2) i = n - 2;
    while (p < tri_start(i, n)) --i;
    while (i < n - 2 && p >= tri_start(i + 1, n)) ++i;
    return i;
}

__global__ __launch_bounds__(BLOCK_THREADS)
void neighborlist_kernel(const float* __restrict__ pos,
                         const float* __restrict__ box,
                         const int*   __restrict__ is_periodic,
                         float* __restrict__ out_i,
                         float* __restrict__ out_j,
                         float* __restrict__ out_d,
                         float* __restrict__ out_r,
                         int n, int P)
{
    const int warp = (blockIdx.x * BLOCK_THREADS + threadIdx.x) >> 5;
    const int lane = threadIdx.x & 31;
    const int wb   = warp * 128;
    if (wb >= P) return;

    // ---- per-lane triangular index at first pair (clamped for tail lanes)
    int p  = wb + lane;
    const int pc = min(p, P - 1);
    int i  = tri_row(pc, n);
    int rs = tri_start(i, n);
    int j  = i + 1 + (pc - rs);

    const float Lx = box[0], Ly = box[4], Lz = box[8];
    const float hx = 0.5f * Lx, hy = 0.5f * Ly, hz = 0.5f * Lz;
    const int per = *is_periodic;

    // largest float s with fl(sqrt(s)) <= 0.5  (== cutoff^2 + 1 ulp)
    const float SMAX = __uint_as_float(0x3E800001u);

    float xi = pos[3 * i + 0], yi = pos[3 * i + 1], zi = pos[3 * i + 2];
    float fi_f = (float)i;
    float fj_f = (float)j;

    // ---- cooperative fast-path store setup (lanes 0..23)
    // lanes 0-7 -> i stream, 8-15 -> j stream, 16-23 -> d stream; 16B each.
    float* ijd_ptr;
    {
        float* sbase = (lane < 8) ? out_i : (lane < 16) ? out_j : out_d;
        ijd_ptr = sbase + wb + 4 * (lane & 7);
    }
    float* r_ptr = out_r + 3 * wb + 4 * lane;            // lanes 0..23
    const float4 cval = (lane < 16) ? make_float4(-1.f, -1.f, -1.f, -1.f)
                                    : make_float4(0.f, 0.f, 0.f, 0.f);
    const float4 zero4 = make_float4(0.f, 0.f, 0.f, 0.f);

    #pragma unroll
    for (int m = 0; m < 4; ++m) {
        const int pb = wb + 32 * m;
        if (pb >= P) break;
        if (m) {
            p += 32;
            j += 32; fj_f += 32.0f;            // exact: j < 2^24
            if (j >= n && p < P) {             // row crossing(s)
                do {
                    rs += n - 1 - i;
                    ++i;
                    j = i + 1 + (p - rs);
                } while (j >= n);
                xi = pos[3 * i + 0]; yi = pos[3 * i + 1]; zi = pos[3 * i + 2];
                fi_f = (float)i; fj_f = (float)j;
            }
        }

        const bool full  = (pb + 32 <= P);
        const bool valid = (p < P);

        float dx = 0.f, dy = 0.f, dz = 0.f, s = 1e30f;
        if (valid) {
            // consecutive lanes: consecutive j -> 12B lane stride, 3 lines/LDG
            dx = xi - pos[3 * j + 0];
            dy = yi - pos[3 * j + 1];
            dz = zi - pos[3 * j + 2];
            if (per) {
                // exact minimum-image for r in (-L, L): t in (-L/2, 3L/2)
                float tx = dx + hx; tx = (tx >= Lx) ? tx - Lx : tx; tx = (tx < 0.0f) ? tx + Lx : tx; dx = tx - hx;
                float ty = dy + hy; ty = (ty >= Ly) ? ty - Ly : ty; ty = (ty < 0.0f) ? ty + Ly : ty; dy = ty - hy;
                float tz = dz + hz; tz = (tz >= Lz) ? tz - Lz : tz; tz = (tz < 0.0f) ? tz + Lz : tz; dz = tz - hz;
            }
            s = dx * dx + dy * dy + dz * dz;   // same contraction as R6
        }
        const bool in = (s <= SMAX);           // == (sqrtf(s) <= 0.5f)

        if (full && !__any_sync(0xffffffffu, in)) {
            // all 32 pairs out of cutoff: constant outputs, 2 x STG.128
            if (lane < 24) {
                __stcs((float4*)ijd_ptr, cval);
                __stcs((float4*)r_ptr,   zero4);
            }
        } else if (valid) {
            const float d = sqrtf(s);          // IEEE; rare path
            __stcs(out_i + p, in ? fi_f : -1.0f);
            __stcs(out_j + p, in ? fj_f : -1.0f);
            __stcs(out_d + p, in ? d    :  0.0f);
            float* rb = out_r + 3 * p;
            __stcs(rb + 0, in ? dx : 0.0f);
            __stcs(rb + 1, in ? dy : 0.0f);
            __stcs(rb + 2, in ? dz : 0.0f);
        }

        ijd_ptr += 32;                         // +128B per iteration
        r_ptr   += 96;                         // +384B per iteration
    }
}

extern "C" void kernel_launch(void* const* d_in, const int* in_sizes, int n_in,
                              void* d_out, int out_size)
{
    const float* pos   = (const float*)d_in[0];
    const float* box   = (const float*)d_in[1];
    const int*   isper = (const int*)d_in[2];
    float*       out   = (float*)d_out;

    const int n = in_sizes[0] / 3;
    const int P = (int)((long long)n * (n - 1) / 2);   // 17,997,000 for n=6000

    const int pairs_per_block = BLOCK_THREADS * 4;     // 1024
    const int grid = (P + pairs_per_block - 1) / pairs_per_block;
    neighborlist_kernel<<<grid, BLOCK_THREADS>>>(pos, box, isper,
                                                 out,
                                                 out + P,
                                                 out + 2 * (size_t)P,
                                                 out + 3 * (size_t)P,
                                                 n, P);
}